// round 15
// baseline (speedup 1.0000x reference)
#include <cuda_runtime.h>
#include <math.h>

#define S 4096
#define L 12
#define CE 64
#define CH 128
#define WE 256
#define HH 512
#define NTAGS 64
#define KC (CE + CH)   // 192
#define KW (CH + WE)   // 384
#define GW 128         // persistent word-LSTM grid (one wave, all resident)

// ---------------- scratch (device globals; no runtime allocation) ----------------
__device__ float g_Bcat[4 * CH * KC];        //  0.4 MB  [Wih1|Whh1], rows permuted unit-major
__device__ float g_b1p[4 * CH];              //  permuted bih1+bhh1
__device__ float g_HcA[S * CH];              //  2.0 MB  char h, buffer A
__device__ float g_HcB[S * CH];              //  2.0 MB  char h, buffer B
__device__ float g_Cc[S * CH];               //  2.0 MB  char c
__device__ float g_xw[(size_t)S * 4 * HH];   // 33.5 MB  word x-gates
__device__ float g_outs[(size_t)S * HH];     //  8.0 MB  word LSTM hidden outputs
__device__ float g_tag[S * NTAGS];           //  1.0 MB
// tagged h exchange: pair = {float bits, step tag}; 2 buffers x 512 pairs
__device__ uint2 g_hpair[2][HH];

__device__ __forceinline__ float sigf(float x) { return 1.f / (1.f + expf(-x)); }
__device__ __forceinline__ float tanha(float x) {
    float y; asm("tanh.approx.f32 %0, %1;" : "=f"(y) : "f"(x)); return y;
}
__device__ __forceinline__ float siga(float x) { return fmaf(tanha(0.5f * x), 0.5f, 0.5f); }

__device__ __forceinline__ uint4 ldv16(const uint4* p) {
    uint4 v;
    asm volatile("ld.volatile.global.v4.u32 {%0,%1,%2,%3}, [%4];"
                 : "=r"(v.x), "=r"(v.y), "=r"(v.z), "=r"(v.w) : "l"(p));
    return v;
}
__device__ __forceinline__ void stcg8(uint2* p, unsigned a, unsigned b) {
    asm volatile("st.global.cg.v2.u32 [%0], {%1,%2};" :: "l"(p), "r"(a), "r"(b) : "memory");
}

// ---------------- fp32 GEMM: C[M,N] = A[M,K] * B[N,K]^T (+b1+b2) ------------------
// Register double-buffered mainloop: next k-tile's global loads issue right after
// the current STS, hiding LDG latency under the 16-k FMA block.
// mode 0: A plain, write C.
// mode 1: A row s = [emb[idx[s*L+l]] | hA[s]] (CE|CH); epilogue = fused char-LSTM
//         update (B rows permuted unit-major, so each thread's 4 cols = i,f,g,o of
//         one unit): c' = sig(f)c + sig(i)tanh(g); hOut = sig(o)tanh(c'). C unused.
// mode 2: A row s = [hA[s] | emb[idx[s]]] (CH|WE); write C.
__global__ void sgemm_tn(int M, int N, int K,
                         const float* __restrict__ A,
                         const float* __restrict__ B,
                         const float* __restrict__ b1,
                         const float* __restrict__ b2,
                         float* __restrict__ C,
                         int mode, const int* __restrict__ idx,
                         const float* __restrict__ emb, int l,
                         const float* __restrict__ hA,
                         float* __restrict__ hOut,
                         float* __restrict__ cSt) {
    __shared__ float As[16][64];
    __shared__ float Bs[16][64];
    const int bn = blockIdx.x * 64, bm = blockIdx.y * 64;
    const int tid = threadIdx.x;
    const int tx = tid & 15, ty = tid >> 4;
    const int lr = tid >> 2, lk = (tid & 3) << 2;

    const int s = bm + lr;
    const float* rA0;
    const float* rA1 = nullptr;
    int split = 1 << 30;
    if (mode == 0) {
        rA0 = A + (size_t)s * K;
    } else if (mode == 1) {
        rA0 = emb + (size_t)idx[s * L + l] * CE;
        rA1 = hA + (size_t)s * CH - CE;
        split = CE;
    } else {
        rA0 = hA + (size_t)s * CH;
        rA1 = emb + (size_t)idx[s] * WE - CH;
        split = CH;
    }
    const float* rB = B + (size_t)(bn + lr) * K;

    float acc[4][4] = {};
    // prologue: load k-tile 0
    float4 a4, b4;
    {
        int d = lk;
        a4 = (d < split) ? *(const float4*)(rA0 + d) : *(const float4*)(rA1 + d);
        b4 = *(const float4*)(rB + d);
    }
    for (int k0 = 0; k0 < K; k0 += 16) {
        As[lk + 0][lr] = a4.x; As[lk + 1][lr] = a4.y;
        As[lk + 2][lr] = a4.z; As[lk + 3][lr] = a4.w;
        Bs[lk + 0][lr] = b4.x; Bs[lk + 1][lr] = b4.y;
        Bs[lk + 2][lr] = b4.z; Bs[lk + 3][lr] = b4.w;
        // prefetch next k-tile (independent of smem compute below)
        if (k0 + 16 < K) {
            int d = k0 + 16 + lk;
            a4 = (d < split) ? *(const float4*)(rA0 + d) : *(const float4*)(rA1 + d);
            b4 = *(const float4*)(rB + d);
        }
        __syncthreads();
#pragma unroll
        for (int k = 0; k < 16; k++) {
            float4 av = *(const float4*)(&As[k][ty << 2]);
            float4 bv = *(const float4*)(&Bs[k][tx << 2]);
            float a[4] = {av.x, av.y, av.z, av.w};
            float b[4] = {bv.x, bv.y, bv.z, bv.w};
#pragma unroll
            for (int i = 0; i < 4; i++)
#pragma unroll
                for (int j = 0; j < 4; j++) acc[i][j] += a[i] * b[j];
        }
        __syncthreads();
    }
    if (mode == 1) {
        // fused char-LSTM pointwise update; cols tx*4..tx*4+3 = gates of unit un
        const int un = (bn >> 2) + tx;
#pragma unroll
        for (int i = 0; i < 4; i++) {
            int row = bm + (ty << 2) + i;
            float gi = acc[i][0] + b1[bn + (tx << 2) + 0];
            float gf = acc[i][1] + b1[bn + (tx << 2) + 1];
            float gg = acc[i][2] + b1[bn + (tx << 2) + 2];
            float go = acc[i][3] + b1[bn + (tx << 2) + 3];
            size_t o = (size_t)row * CH + un;
            float c = cSt[o];
            c = sigf(gf) * c + sigf(gi) * tanhf(gg);
            cSt[o] = c;
            hOut[o] = sigf(go) * tanhf(c);
        }
        return;
    }
#pragma unroll
    for (int i = 0; i < 4; i++) {
        int row = bm + (ty << 2) + i;
#pragma unroll
        for (int j = 0; j < 4; j++) {
            int col = bn + (tx << 2) + j;
            float v = acc[i][j];
            if (b1) v += b1[col];
            if (b2) v += b2[col];
            C[(size_t)row * N + col] = v;
        }
    }
}

// ---------------- small prep kernels ----------------
// permuted Bcat: out row n' = u*4+t  <-  original gate row r = t*CH+u
__global__ void k_bcat(const float* __restrict__ Wih1, const float* __restrict__ Whh1,
                       const float* __restrict__ bih1, const float* __restrict__ bhh1) {
    int i = blockIdx.x * 256 + threadIdx.x;
    if (i >= 4 * CH * KC) return;
    int n = i / KC, d = i % KC;
    int t = n & 3, u = n >> 2;
    int r = t * CH + u;
    g_Bcat[i] = (d < CE) ? Wih1[r * CE + d] : Whh1[r * CH + d - CE];
    if (d == 0) g_b1p[n] = bih1[r] + bhh1[r];
}

__global__ void k_init_char(const float* __restrict__ c_hx0, const float* __restrict__ c_cx0) {
    int i = blockIdx.x * 256 + threadIdx.x;
    if (i >= S * CH) return;
    int j = i & (CH - 1);
    g_HcA[i] = c_hx0[j];
    g_Cc[i] = c_cx0[j];
}

__global__ void k_init_word(const float* __restrict__ hx0) {
    int i = threadIdx.x;  // 512 threads
    g_hpair[0][i] = make_uint2(__float_as_uint(hx0[i]), 0u);
    g_hpair[1][i] = make_uint2(0u, 0x80000000u);
}

// ---------------- persistent word-level LSTM (sequential recurrence) ----------------
// 128 CTAs x 128 threads. Warp u owns hidden unit blk*4+u END-TO-END: computes its 4
// gate rows, reduces in-warp, applies activations redundantly in all lanes, lane 0
// publishes. Only ONE __syncthreads per step (h staging among 4 warps). Sync across
// CTAs: tagged 8B pairs {h_bits, step}; unthrottled ld.volatile polling.
__global__ void __launch_bounds__(128, 1) k_word(const float* __restrict__ Whh2,
                                                 const float* __restrict__ cx0) {
    __shared__ __align__(16) float hs[HH];
    const int blk = blockIdx.x;
    const int tid = threadIdx.x;
    const int w = tid >> 5, lane = tid & 31;
    const int unit = blk * 4 + w;

    // weights: gate row t of this unit -> Whh2 row t*HH + unit; lane l holds
    // W2[t][k] = Whh2[row][64k + 2l .. +1]  (16 floats per lane per row)
    float2 W2[4][8];
#pragma unroll
    for (int t = 0; t < 4; t++) {
        const float* wr = Whh2 + (size_t)(t * HH + unit) * HH + 2 * lane;
#pragma unroll
        for (int k = 0; k < 8; k++)
            W2[t][k] = *(const float2*)(wr + 64 * k);
    }

    float c_u = cx0[unit];   // replicated across lanes

    // x-gates for this unit: xg[t] = g_xw[s*2048 + t*512 + unit] (uniform per warp)
    float xg[4];
#pragma unroll
    for (int t = 0; t < 4; t++) xg[t] = __ldg(g_xw + t * HH + unit);

    for (int s = 0; s < S; s++) {
        // prefetch next step's x-gates (overlaps the poll)
        float xn[4];
        {
            int sn = (s + 1 < S) ? s + 1 : s;
            const float* xp = g_xw + (size_t)sn * 2048 + unit;
#pragma unroll
            for (int t = 0; t < 4; t++) xn[t] = __ldg(xp + t * HH);
        }
        // poll 4 tagged pairs per thread (2x16B, coalesced), stage h into smem
        const uint4* src = (const uint4*)(g_hpair[s & 1] + 4 * tid);
        const unsigned tg = (unsigned)s;
        uint4 v0, v1;
        do {
            v0 = ldv16(src);
            v1 = ldv16(src + 1);
        } while (v0.y != tg || v0.w != tg || v1.y != tg || v1.w != tg);
        *(float4*)&hs[4 * tid] = make_float4(__uint_as_float(v0.x), __uint_as_float(v0.z),
                                             __uint_as_float(v1.x), __uint_as_float(v1.z));
        __syncthreads();

        // dot products: 4 gate rows, lane l covers h[64k+2l..+1], k=0..7
        float2 h2[8];
#pragma unroll
        for (int k = 0; k < 8; k++)
            h2[k] = *(const float2*)&hs[64 * k + 2 * lane];
        float g0, g1, g2, g3;
        {
            float a0 = 0.f, b0 = 0.f, a1 = 0.f, b1_ = 0.f;
            float a2 = 0.f, b2_ = 0.f, a3 = 0.f, b3 = 0.f;
#pragma unroll
            for (int k = 0; k < 8; k++) {
                a0 = fmaf(W2[0][k].x, h2[k].x, a0);  b0 = fmaf(W2[0][k].y, h2[k].y, b0);
                a1 = fmaf(W2[1][k].x, h2[k].x, a1);  b1_ = fmaf(W2[1][k].y, h2[k].y, b1_);
                a2 = fmaf(W2[2][k].x, h2[k].x, a2);  b2_ = fmaf(W2[2][k].y, h2[k].y, b2_);
                a3 = fmaf(W2[3][k].x, h2[k].x, a3);  b3 = fmaf(W2[3][k].y, h2[k].y, b3);
            }
            g0 = a0 + b0; g1 = a1 + b1_; g2 = a2 + b2_; g3 = a3 + b3;
        }
        // 4 pipelined butterfly reductions (every lane ends with the full sums)
#pragma unroll
        for (int o = 16; o; o >>= 1) {
            g0 += __shfl_xor_sync(0xffffffffu, g0, o);
            g1 += __shfl_xor_sync(0xffffffffu, g1, o);
            g2 += __shfl_xor_sync(0xffffffffu, g2, o);
            g3 += __shfl_xor_sync(0xffffffffu, g3, o);
        }
        // activations, redundant in all lanes (no broadcast needed)
        float ai = siga(g0 + xg[0]);
        float af = siga(g1 + xg[1]);
        float ag = tanha(g2 + xg[2]);
        float ao = siga(g3 + xg[3]);
        c_u = fmaf(af, c_u, ai * ag);
        float hv = ao * tanha(c_u);
        if (lane == 0)
            stcg8(&g_hpair[(s + 1) & 1][unit], __float_as_uint(hv), (unsigned)(s + 1));
        else if (lane == 1)
            g_outs[(size_t)s * HH + unit] = hv;
        xg[0] = xn[0]; xg[1] = xn[1]; xg[2] = xn[2]; xg[3] = xn[3];
    }
}

// ---------------- log-softmax over 64 tags, one warp per row ----------------
__global__ void k_logsoftmax(float* __restrict__ out) {
    int row = blockIdx.x * 4 + (threadIdx.x >> 5);
    int lane = threadIdx.x & 31;
    const float* t = g_tag + (size_t)row * NTAGS;
    float v0 = t[lane], v1 = t[lane + 32];
    float m = fmaxf(v0, v1);
#pragma unroll
    for (int o = 16; o; o >>= 1) m = fmaxf(m, __shfl_xor_sync(0xffffffffu, m, o));
    float e = expf(v0 - m) + expf(v1 - m);
#pragma unroll
    for (int o = 16; o; o >>= 1) e += __shfl_xor_sync(0xffffffffu, e, o);
    float lse = m + logf(e);
    out[(size_t)row * NTAGS + lane] = v0 - lse;
    out[(size_t)row * NTAGS + lane + 32] = v1 - lse;
}

// ---------------- launch ----------------
extern "C" void kernel_launch(void* const* d_in, const int* in_sizes, int n_in,
                              void* d_out, int out_size) {
    const int*   w_seq    = (const int*)d_in[0];
    const int*   c_seq    = (const int*)d_in[1];
    const float* char_emb = (const float*)d_in[2];
    const float* word_emb = (const float*)d_in[3];
    const float* c_hx0    = (const float*)d_in[4];
    const float* c_cx0    = (const float*)d_in[5];
    const float* hx0      = (const float*)d_in[6];
    const float* cx0      = (const float*)d_in[7];
    const float* Wih1     = (const float*)d_in[8];
    const float* Whh1     = (const float*)d_in[9];
    const float* bih1     = (const float*)d_in[10];
    const float* bhh1     = (const float*)d_in[11];
    const float* Wih2     = (const float*)d_in[12];
    const float* Whh2     = (const float*)d_in[13];
    const float* bih2     = (const float*)d_in[14];
    const float* bhh2     = (const float*)d_in[15];
    const float* W_out    = (const float*)d_in[16];
    const float* b_out    = (const float*)d_in[17];
    float* out = (float*)d_out;

    void *pB, *pb1, *pHA, *pHB, *pCc, *pX, *pO, *pT;
    cudaGetSymbolAddress(&pB, g_Bcat);
    cudaGetSymbolAddress(&pb1, g_b1p);
    cudaGetSymbolAddress(&pHA, g_HcA);
    cudaGetSymbolAddress(&pHB, g_HcB);
    cudaGetSymbolAddress(&pCc, g_Cc);
    cudaGetSymbolAddress(&pX, g_xw);
    cudaGetSymbolAddress(&pO, g_outs);
    cudaGetSymbolAddress(&pT, g_tag);

    k_bcat<<<(4 * CH * KC + 255) / 256, 256>>>(Wih1, Whh1, bih1, bhh1);
    k_init_char<<<(S * CH + 255) / 256, 256>>>(c_hx0, c_cx0);

    // char LSTM: 12 steps, gather + GEMM + pointwise update fused (mode 1),
    // h double-buffered A->B->A->... (L=12 even: final h in buffer A)
    for (int l = 0; l < L; l++) {
        const float* hin  = (l & 1) ? (const float*)pHB : (const float*)pHA;
        float*       hout = (l & 1) ? (float*)pHA : (float*)pHB;
        sgemm_tn<<<dim3(4 * CH / 64, S / 64), 256>>>(S, 4 * CH, KC,
            nullptr, (const float*)pB, (const float*)pb1, nullptr, nullptr,
            1, c_seq, char_emb, l, hin, hout, (float*)pCc);
    }

    // word x-gates, A gathered in-GEMM (mode 2), char h from buffer A
    sgemm_tn<<<dim3(4 * HH / 64, S / 64), 256>>>(S, 4 * HH, KW,
        nullptr, Wih2, bih2, bhh2, (float*)pX,
        2, w_seq, word_emb, 0, (const float*)pHA, nullptr, nullptr);

    // sequential word LSTM (persistent, tag-synchronized, warp-per-unit)
    k_init_word<<<1, 512>>>(hx0);
    k_word<<<GW, 128>>>(Whh2, cx0);

    // tags + log-softmax
    sgemm_tn<<<dim3(NTAGS / 64, S / 64), 256>>>(S, NTAGS, HH,
        (const float*)pO, W_out, b_out, nullptr, (float*)pT,
        0, nullptr, nullptr, 0, nullptr, nullptr, nullptr);
    k_logsoftmax<<<S / 4, 128>>>(out);
}

// round 16
// speedup vs baseline: 1.3008x; 1.3008x over previous
#include <cuda_runtime.h>
#include <math.h>

#define S 4096
#define L 12
#define CE 64
#define CH 128
#define WE 256
#define HH 512
#define NTAGS 64
#define KC (CE + CH)   // 192
#define KW (CH + WE)   // 384
#define GW 128         // persistent word-LSTM grid (one wave, all resident)

// ---------------- scratch (device globals; no runtime allocation) ----------------
__device__ float g_Bcat[4 * CH * KC];        //  0.4 MB  [Wih1|Whh1], rows permuted unit-major
__device__ float g_b1p[4 * CH];              //  permuted bih1+bhh1
__device__ float g_HcA[S * CH];              //  2.0 MB  char h, buffer A
__device__ float g_HcB[S * CH];              //  2.0 MB  char h, buffer B
__device__ float g_Cc[S * CH];               //  2.0 MB  char c
__device__ float g_xw[(size_t)S * 4 * HH];   // 33.5 MB  word x-gates
__device__ float g_outs[(size_t)S * HH];     //  8.0 MB  word LSTM hidden outputs
__device__ float g_tag[S * NTAGS];           //  1.0 MB
// tagged h exchange: pair = {float bits, step tag}; 2 buffers x 512 pairs
__device__ uint2 g_hpair[2][HH];

__device__ __forceinline__ float sigf(float x) { return 1.f / (1.f + expf(-x)); }
__device__ __forceinline__ float tanha(float x) {
    float y; asm("tanh.approx.f32 %0, %1;" : "=f"(y) : "f"(x)); return y;
}
__device__ __forceinline__ float siga(float x) { return fmaf(tanha(0.5f * x), 0.5f, 0.5f); }

__device__ __forceinline__ uint4 ldv16(const uint4* p) {
    uint4 v;
    asm volatile("ld.volatile.global.v4.u32 {%0,%1,%2,%3}, [%4];"
                 : "=r"(v.x), "=r"(v.y), "=r"(v.z), "=r"(v.w) : "l"(p));
    return v;
}
__device__ __forceinline__ void stcg8(uint2* p, unsigned a, unsigned b) {
    asm volatile("st.global.cg.v2.u32 [%0], {%1,%2};" :: "l"(p), "r"(a), "r"(b) : "memory");
}

// ---------------- fp32 GEMM: C[M,N] = A[M,K] * B[N,K]^T (+b1+b2) ------------------
// mode 0: A plain, write C.
// mode 1: A row s = [emb[idx[s*L+l]] | hA[s]] (CE|CH); epilogue = fused char-LSTM
//         update (B rows permuted unit-major, so each thread's 4 cols = i,f,g,o of
//         one unit): c' = sig(f)c + sig(i)tanh(g); hOut = sig(o)tanh(c'). C unused.
// mode 2: A row s = [hA[s] | emb[idx[s]]] (CH|WE); write C.
__global__ void sgemm_tn(int M, int N, int K,
                         const float* __restrict__ A,
                         const float* __restrict__ B,
                         const float* __restrict__ b1,
                         const float* __restrict__ b2,
                         float* __restrict__ C,
                         int mode, const int* __restrict__ idx,
                         const float* __restrict__ emb, int l,
                         const float* __restrict__ hA,
                         float* __restrict__ hOut,
                         float* __restrict__ cSt) {
    __shared__ float As[16][64];
    __shared__ float Bs[16][64];
    const int bn = blockIdx.x * 64, bm = blockIdx.y * 64;
    const int tid = threadIdx.x;
    const int tx = tid & 15, ty = tid >> 4;
    const int lr = tid >> 2, lk = (tid & 3) << 2;

    const int s = bm + lr;
    const float* rA0;
    const float* rA1 = nullptr;
    int split = 1 << 30;
    if (mode == 0) {
        rA0 = A + (size_t)s * K;
    } else if (mode == 1) {
        rA0 = emb + (size_t)idx[s * L + l] * CE;
        rA1 = hA + (size_t)s * CH - CE;
        split = CE;
    } else {
        rA0 = hA + (size_t)s * CH;
        rA1 = emb + (size_t)idx[s] * WE - CH;
        split = CH;
    }
    const float* rB = B + (size_t)(bn + lr) * K;

    float acc[4][4] = {};
    for (int k0 = 0; k0 < K; k0 += 16) {
        int d = k0 + lk;
        float4 a4 = (d < split) ? *(const float4*)(rA0 + d) : *(const float4*)(rA1 + d);
        float4 b4 = *(const float4*)(rB + d);
        As[lk + 0][lr] = a4.x; As[lk + 1][lr] = a4.y;
        As[lk + 2][lr] = a4.z; As[lk + 3][lr] = a4.w;
        Bs[lk + 0][lr] = b4.x; Bs[lk + 1][lr] = b4.y;
        Bs[lk + 2][lr] = b4.z; Bs[lk + 3][lr] = b4.w;
        __syncthreads();
#pragma unroll
        for (int k = 0; k < 16; k++) {
            float4 av = *(const float4*)(&As[k][ty << 2]);
            float4 bv = *(const float4*)(&Bs[k][tx << 2]);
            float a[4] = {av.x, av.y, av.z, av.w};
            float b[4] = {bv.x, bv.y, bv.z, bv.w};
#pragma unroll
            for (int i = 0; i < 4; i++)
#pragma unroll
                for (int j = 0; j < 4; j++) acc[i][j] += a[i] * b[j];
        }
        __syncthreads();
    }
    if (mode == 1) {
        // fused char-LSTM pointwise update; cols tx*4..tx*4+3 = gates of unit un
        const int un = (bn >> 2) + tx;
#pragma unroll
        for (int i = 0; i < 4; i++) {
            int row = bm + (ty << 2) + i;
            float gi = acc[i][0] + b1[bn + (tx << 2) + 0];
            float gf = acc[i][1] + b1[bn + (tx << 2) + 1];
            float gg = acc[i][2] + b1[bn + (tx << 2) + 2];
            float go = acc[i][3] + b1[bn + (tx << 2) + 3];
            size_t o = (size_t)row * CH + un;
            float c = cSt[o];
            c = sigf(gf) * c + sigf(gi) * tanhf(gg);
            cSt[o] = c;
            hOut[o] = sigf(go) * tanhf(c);
        }
        return;
    }
#pragma unroll
    for (int i = 0; i < 4; i++) {
        int row = bm + (ty << 2) + i;
#pragma unroll
        for (int j = 0; j < 4; j++) {
            int col = bn + (tx << 2) + j;
            float v = acc[i][j];
            if (b1) v += b1[col];
            if (b2) v += b2[col];
            C[(size_t)row * N + col] = v;
        }
    }
}

// ---------------- small prep kernels ----------------
// permuted Bcat: out row n' = u*4+t  <-  original gate row r = t*CH+u
__global__ void k_bcat(const float* __restrict__ Wih1, const float* __restrict__ Whh1,
                       const float* __restrict__ bih1, const float* __restrict__ bhh1) {
    int i = blockIdx.x * 256 + threadIdx.x;
    if (i >= 4 * CH * KC) return;
    int n = i / KC, d = i % KC;
    int t = n & 3, u = n >> 2;
    int r = t * CH + u;
    g_Bcat[i] = (d < CE) ? Wih1[r * CE + d] : Whh1[r * CH + d - CE];
    if (d == 0) g_b1p[n] = bih1[r] + bhh1[r];
}

__global__ void k_init_char(const float* __restrict__ c_hx0, const float* __restrict__ c_cx0) {
    int i = blockIdx.x * 256 + threadIdx.x;
    if (i >= S * CH) return;
    int j = i & (CH - 1);
    g_HcA[i] = c_hx0[j];
    g_Cc[i] = c_cx0[j];
}

__global__ void k_init_word(const float* __restrict__ hx0) {
    int i = threadIdx.x;  // 512 threads
    g_hpair[0][i] = make_uint2(__float_as_uint(hx0[i]), 0u);
    g_hpair[1][i] = make_uint2(0u, 0x80000000u);
}

// ---------------- persistent word-level LSTM (sequential recurrence) ----------------
// 128 CTAs x 128 threads. Warp u owns hidden unit blk*4+u END-TO-END: computes its 4
// gate rows, reduces in-warp, applies activations redundantly in all lanes, lane 0
// publishes. Only ONE __syncthreads per step (h staging among 4 warps). Sync across
// CTAs: tagged 8B pairs {h_bits, step}; unthrottled ld.volatile polling.
__global__ void __launch_bounds__(128, 1) k_word(const float* __restrict__ Whh2,
                                                 const float* __restrict__ cx0) {
    __shared__ __align__(16) float hs[HH];
    const int blk = blockIdx.x;
    const int tid = threadIdx.x;
    const int w = tid >> 5, lane = tid & 31;
    const int unit = blk * 4 + w;

    // weights: gate row t of this unit -> Whh2 row t*HH + unit; lane l holds
    // W2[t][k] = Whh2[row][64k + 2l .. +1]  (16 floats per lane per row)
    float2 W2[4][8];
#pragma unroll
    for (int t = 0; t < 4; t++) {
        const float* wr = Whh2 + (size_t)(t * HH + unit) * HH + 2 * lane;
#pragma unroll
        for (int k = 0; k < 8; k++)
            W2[t][k] = *(const float2*)(wr + 64 * k);
    }

    float c_u = cx0[unit];   // replicated across lanes

    // x-gates for this unit: xg[t] = g_xw[s*2048 + t*512 + unit] (uniform per warp)
    float xg[4];
#pragma unroll
    for (int t = 0; t < 4; t++) xg[t] = __ldg(g_xw + t * HH + unit);

    for (int s = 0; s < S; s++) {
        // prefetch next step's x-gates (overlaps the poll)
        float xn[4];
        {
            int sn = (s + 1 < S) ? s + 1 : s;
            const float* xp = g_xw + (size_t)sn * 2048 + unit;
#pragma unroll
            for (int t = 0; t < 4; t++) xn[t] = __ldg(xp + t * HH);
        }
        // poll 4 tagged pairs per thread (2x16B, coalesced), stage h into smem
        const uint4* src = (const uint4*)(g_hpair[s & 1] + 4 * tid);
        const unsigned tg = (unsigned)s;
        uint4 v0, v1;
        do {
            v0 = ldv16(src);
            v1 = ldv16(src + 1);
        } while (v0.y != tg || v0.w != tg || v1.y != tg || v1.w != tg);
        *(float4*)&hs[4 * tid] = make_float4(__uint_as_float(v0.x), __uint_as_float(v0.z),
                                             __uint_as_float(v1.x), __uint_as_float(v1.z));
        __syncthreads();

        // dot products: 4 gate rows, lane l covers h[64k+2l..+1], k=0..7
        float2 h2[8];
#pragma unroll
        for (int k = 0; k < 8; k++)
            h2[k] = *(const float2*)&hs[64 * k + 2 * lane];
        float g0, g1, g2, g3;
        {
            float a0 = 0.f, b0 = 0.f, a1 = 0.f, b1_ = 0.f;
            float a2 = 0.f, b2_ = 0.f, a3 = 0.f, b3 = 0.f;
#pragma unroll
            for (int k = 0; k < 8; k++) {
                a0 = fmaf(W2[0][k].x, h2[k].x, a0);  b0 = fmaf(W2[0][k].y, h2[k].y, b0);
                a1 = fmaf(W2[1][k].x, h2[k].x, a1);  b1_ = fmaf(W2[1][k].y, h2[k].y, b1_);
                a2 = fmaf(W2[2][k].x, h2[k].x, a2);  b2_ = fmaf(W2[2][k].y, h2[k].y, b2_);
                a3 = fmaf(W2[3][k].x, h2[k].x, a3);  b3 = fmaf(W2[3][k].y, h2[k].y, b3);
            }
            g0 = a0 + b0; g1 = a1 + b1_; g2 = a2 + b2_; g3 = a3 + b3;
        }
        // 4 pipelined butterfly reductions (every lane ends with the full sums)
#pragma unroll
        for (int o = 16; o; o >>= 1) {
            g0 += __shfl_xor_sync(0xffffffffu, g0, o);
            g1 += __shfl_xor_sync(0xffffffffu, g1, o);
            g2 += __shfl_xor_sync(0xffffffffu, g2, o);
            g3 += __shfl_xor_sync(0xffffffffu, g3, o);
        }
        // activations, redundant in all lanes (no broadcast needed)
        float ai = siga(g0 + xg[0]);
        float af = siga(g1 + xg[1]);
        float ag = tanha(g2 + xg[2]);
        float ao = siga(g3 + xg[3]);
        c_u = fmaf(af, c_u, ai * ag);
        float hv = ao * tanha(c_u);
        if (lane == 0)
            stcg8(&g_hpair[(s + 1) & 1][unit], __float_as_uint(hv), (unsigned)(s + 1));
        else if (lane == 1)
            g_outs[(size_t)s * HH + unit] = hv;
        xg[0] = xn[0]; xg[1] = xn[1]; xg[2] = xn[2]; xg[3] = xn[3];
    }
}

// ---------------- log-softmax over 64 tags, one warp per row ----------------
__global__ void k_logsoftmax(float* __restrict__ out) {
    int row = blockIdx.x * 4 + (threadIdx.x >> 5);
    int lane = threadIdx.x & 31;
    const float* t = g_tag + (size_t)row * NTAGS;
    float v0 = t[lane], v1 = t[lane + 32];
    float m = fmaxf(v0, v1);
#pragma unroll
    for (int o = 16; o; o >>= 1) m = fmaxf(m, __shfl_xor_sync(0xffffffffu, m, o));
    float e = expf(v0 - m) + expf(v1 - m);
#pragma unroll
    for (int o = 16; o; o >>= 1) e += __shfl_xor_sync(0xffffffffu, e, o);
    float lse = m + logf(e);
    out[(size_t)row * NTAGS + lane] = v0 - lse;
    out[(size_t)row * NTAGS + lane + 32] = v1 - lse;
}

// ---------------- launch ----------------
extern "C" void kernel_launch(void* const* d_in, const int* in_sizes, int n_in,
                              void* d_out, int out_size) {
    const int*   w_seq    = (const int*)d_in[0];
    const int*   c_seq    = (const int*)d_in[1];
    const float* char_emb = (const float*)d_in[2];
    const float* word_emb = (const float*)d_in[3];
    const float* c_hx0    = (const float*)d_in[4];
    const float* c_cx0    = (const float*)d_in[5];
    const float* hx0      = (const float*)d_in[6];
    const float* cx0      = (const float*)d_in[7];
    const float* Wih1     = (const float*)d_in[8];
    const float* Whh1     = (const float*)d_in[9];
    const float* bih1     = (const float*)d_in[10];
    const float* bhh1     = (const float*)d_in[11];
    const float* Wih2     = (const float*)d_in[12];
    const float* Whh2     = (const float*)d_in[13];
    const float* bih2     = (const float*)d_in[14];
    const float* bhh2     = (const float*)d_in[15];
    const float* W_out    = (const float*)d_in[16];
    const float* b_out    = (const float*)d_in[17];
    float* out = (float*)d_out;

    void *pB, *pb1, *pHA, *pHB, *pCc, *pX, *pO, *pT;
    cudaGetSymbolAddress(&pB, g_Bcat);
    cudaGetSymbolAddress(&pb1, g_b1p);
    cudaGetSymbolAddress(&pHA, g_HcA);
    cudaGetSymbolAddress(&pHB, g_HcB);
    cudaGetSymbolAddress(&pCc, g_Cc);
    cudaGetSymbolAddress(&pX, g_xw);
    cudaGetSymbolAddress(&pO, g_outs);
    cudaGetSymbolAddress(&pT, g_tag);

    k_bcat<<<(4 * CH * KC + 255) / 256, 256>>>(Wih1, Whh1, bih1, bhh1);
    k_init_char<<<(S * CH + 255) / 256, 256>>>(c_hx0, c_cx0);

    // char LSTM: 12 steps, gather + GEMM + pointwise update fused (mode 1),
    // h double-buffered A->B->A->... (L=12 even: final h in buffer A)
    for (int l = 0; l < L; l++) {
        const float* hin  = (l & 1) ? (const float*)pHB : (const float*)pHA;
        float*       hout = (l & 1) ? (float*)pHA : (float*)pHB;
        sgemm_tn<<<dim3(4 * CH / 64, S / 64), 256>>>(S, 4 * CH, KC,
            nullptr, (const float*)pB, (const float*)pb1, nullptr, nullptr,
            1, c_seq, char_emb, l, hin, hout, (float*)pCc);
    }

    // word x-gates, A gathered in-GEMM (mode 2), char h from buffer A
    sgemm_tn<<<dim3(4 * HH / 64, S / 64), 256>>>(S, 4 * HH, KW,
        nullptr, Wih2, bih2, bhh2, (float*)pX,
        2, w_seq, word_emb, 0, (const float*)pHA, nullptr, nullptr);

    // sequential word LSTM (persistent, tag-synchronized, warp-per-unit)
    k_init_word<<<1, 512>>>(hx0);
    k_word<<<GW, 128>>>(Whh2, cx0);

    // tags + log-softmax
    sgemm_tn<<<dim3(NTAGS / 64, S / 64), 256>>>(S, NTAGS, HH,
        (const float*)pO, W_out, b_out, nullptr, (float*)pT,
        0, nullptr, nullptr, 0, nullptr, nullptr, nullptr);
    k_logsoftmax<<<S / 4, 128>>>(out);
}